// round 16
// baseline (speedup 1.0000x reference)
#include <cuda_runtime.h>

// TrajectoryGeneratorAR_goal: S=256 rollouts x N=64 agents, OBS=8 encoder LSTM
// steps, PRED=12 autoregressive decoder steps with pairwise pooling net.
// Round 16 = R15 winner (1428us: 128 CTAs x 384 thr, 2 samples/CTA, tile-3
// pooling, 168 regs) with the zero-weight pads removed: floor(mycnt/3) full
// tile-3 iterations + an EXACT tile-1 tail (<=2 real pairs). Pads were ~8-9%
// dummy FLOPs per step (full 2080-FMA k-loops multiplied by 0).

namespace {

constexpr int S_BATCH  = 256;
constexpr int NAG      = 64;     // agents per sample
constexpr int NAGC     = 128;    // agents per CTA (2 samples)
constexpr int BTOT     = S_BATCH * NAG;   // 16384
constexpr int OBS      = 8;
constexpr int PRED     = 12;
constexpr int H        = 16;
constexpr int NTHREADS = 384;
constexpr int NCTAS    = S_BATCH / 2;     // 128
constexpr int MAXPAIRS = NAGC * NAG;      // 8192

struct __align__(16) Smem {
    float h[NAGC][17];
    float c[NAGC][17];
    float ctx[NAGC][17];
    float hjp[NAGC][65];
    float curr[NAGC][2];
    float outp[NAGC][2];
    float goal[NAGC][2];
    unsigned long long nmask[NAGC];
    int   pfx[NAGC + 1];
    unsigned short plist[MAXPAIRS];   // (i<<7)|j, sorted by i
    alignas(16) float embW[32];
    alignas(16) float embB[16];
    alignas(16) float encWih[16*64];
    alignas(16) float encWhh[16*64];
    alignas(16) float encB[64];
    alignas(16) float decinW[18*16];
    alignas(16) float decinB[16];
    alignas(16) float decWih[16*64];
    alignas(16) float decWhh[16*64];
    alignas(16) float decB[64];
    alignas(16) float peW[32];
    alignas(16) float peB[16];
    alignas(16) float W1pT[64*16];   // [k][d]  (pool_W1 rows 0..15, transposed)
    alignas(16) float W1h [16*64];   // [d][k]  (pool_W1 rows 16..31)
    alignas(16) float b1  [64];
    alignas(16) float W2  [64*16];   // [k][u]
    alignas(16) float b2  [16];
    alignas(16) float h2p1W[18*16];
    alignas(16) float h2p1B[16];
    alignas(16) float h2p2W[16*4];
    alignas(16) float h2p2B[4];
};

__device__ __forceinline__ float sigm(float x)   { return 1.0f / (1.0f + __expf(-x)); }
__device__ __forceinline__ float tanh_f(float x) { return 2.0f / (1.0f + __expf(-2.0f * x)) - 1.0f; }

__device__ __forceinline__ void cpw(float* dst, const float* src, int n, int tid) {
    for (int k = tid; k < n; k += NTHREADS) dst[k] = src[k];
}

} // namespace

__global__ __launch_bounds__(NTHREADS, 1)
void traj_ar_kernel(
    const float* __restrict__ traj_rel,
    const float* __restrict__ obs_pos,
    const float* __restrict__ goal_g,
    const float* __restrict__ embW, const float* __restrict__ embB,
    const float* __restrict__ encWih, const float* __restrict__ encWhh, const float* __restrict__ encB,
    const float* __restrict__ decinW, const float* __restrict__ decinB,
    const float* __restrict__ decWih, const float* __restrict__ decWhh, const float* __restrict__ decB,
    const float* __restrict__ peW, const float* __restrict__ peB,
    const float* __restrict__ W1, const float* __restrict__ b1,
    const float* __restrict__ W2, const float* __restrict__ b2,
    const float* __restrict__ h2p1W, const float* __restrict__ h2p1B,
    const float* __restrict__ h2p2W, const float* __restrict__ h2p2B,
    const int* __restrict__ nei,
    float* __restrict__ out, int out_size)
{
    extern __shared__ unsigned char smem_raw[];
    Smem& sm = *reinterpret_cast<Smem*>(smem_raw);
    const int tid = threadIdx.x;
    const int sb  = blockIdx.x;           // CTA handles samples 2sb, 2sb+1
    const int gb  = sb * NAGC;

    if (sb == 0 && tid == 0) {
        for (int idx = PRED * BTOT * 2; idx < out_size; ++idx) out[idx] = 0.0f;
    }

    // ---------------- weight staging + state init ----------------
    cpw(sm.embW,  embW,  32,  tid);  cpw(sm.embB,  embB,  16, tid);
    cpw(sm.encWih, encWih, 1024, tid); cpw(sm.encWhh, encWhh, 1024, tid); cpw(sm.encB, encB, 64, tid);
    cpw(sm.decinW, decinW, 288, tid);  cpw(sm.decinB, decinB, 16, tid);
    cpw(sm.decWih, decWih, 1024, tid); cpw(sm.decWhh, decWhh, 1024, tid); cpw(sm.decB, decB, 64, tid);
    cpw(sm.peW, peW, 32, tid); cpw(sm.peB, peB, 16, tid);
    for (int idx = tid; idx < 1024; idx += NTHREADS) {
        const int k = idx >> 4, d = idx & 15;
        sm.W1pT[idx] = W1[d * 64 + k];
    }
    cpw(sm.W1h, W1 + 1024, 1024, tid);
    cpw(sm.b1, b1, 64, tid); cpw(sm.W2, W2, 1024, tid); cpw(sm.b2, b2, 16, tid);
    cpw(sm.h2p1W, h2p1W, 288, tid); cpw(sm.h2p1B, h2p1B, 16, tid);
    cpw(sm.h2p2W, h2p2W, 64, tid);  cpw(sm.h2p2B, h2p2B, 4, tid);

    for (int idx = tid; idx < NAGC * 17; idx += NTHREADS) {
        (&sm.h[0][0])[idx] = 0.0f; (&sm.c[0][0])[idx] = 0.0f; (&sm.ctx[0][0])[idx] = 0.0f;
    }
    if (tid < NAGC) {
        sm.nmask[tid] = 0ull;
        const int b = gb + tid;
        const float c0 = obs_pos[((OBS - 1) * BTOT + b) * 2 + 0];
        const float c1 = obs_pos[((OBS - 1) * BTOT + b) * 2 + 1];
        sm.curr[tid][0] = c0; sm.curr[tid][1] = c1;
        sm.outp[tid][0] = traj_rel[((OBS - 1) * BTOT + b) * 2 + 0];
        sm.outp[tid][1] = traj_rel[((OBS - 1) * BTOT + b) * 2 + 1];
        sm.goal[tid][0] = goal_g[b * 2 + 0] - c0;
        sm.goal[tid][1] = goal_g[b * 2 + 1] - c1;
    }
    __syncthreads();
    {   // neighbor masks for both samples: row i (0..127), local j (0..63)
        const int base = gb * NAG;
        for (int flat = tid; flat < NAGC * NAG; flat += NTHREADS) {
            if (nei[base + flat] != 0)
                atomicOr(&sm.nmask[flat >> 6], 1ull << (flat & 63));
        }
    }
    __syncthreads();
    // ---- compacted (i, j_global) pair list, sorted by i ----
    if (tid == 0) {
        int run = 0;
        for (int i = 0; i < NAGC; ++i) { sm.pfx[i] = run; run += __popcll(sm.nmask[i]); }
        sm.pfx[NAGC] = run;
    }
    __syncthreads();
    if (tid < NAGC) {
        unsigned long long m = sm.nmask[tid];
        int w = sm.pfx[tid];
        const int jbase = tid & 64;                // sample offset for j
        const unsigned short ibase = (unsigned short)(tid << 7);
        while (m) {
            const int j = __ffsll((long long)m) - 1;
            m &= m - 1;
            sm.plist[w++] = (unsigned short)(ibase | (unsigned short)(jbase + j));
        }
    }
    __syncthreads();
    const int P       = sm.pfx[NAGC];
    const int pbase   = P / NTHREADS;
    const int prem    = P - pbase * NTHREADS;
    const int mystart = tid * pbase + (tid < prem ? tid : prem);
    const int mycnt   = pbase + (tid < prem ? 1 : 0);
    const int mymain  = mycnt - (mycnt % 3);   // full tile-3 part

    // LSTM phase layout: 2 threads per agent (tid < 256), 8 gate units each
    const int a2   = tid >> 1;
    const int sub2 = tid & 1;
    const bool lstm_active = (tid < 2 * NAGC);

    // ---------------- history encoder ----------------
    if (lstm_active) {
        for (int t = 0; t < OBS; ++t) {
            const int b = gb + a2;
            const float x0 = traj_rel[(t * BTOT + b) * 2 + 0];
            const float x1 = traj_rel[(t * BTOT + b) * 2 + 1];
            float emb[H];
            #pragma unroll
            for (int u = 0; u < H; ++u)
                emb[u] = fmaxf(fmaf(x0, sm.embW[u], fmaf(x1, sm.embW[16 + u], sm.embB[u])), 0.0f);
            float hold[H];
            #pragma unroll
            for (int d = 0; d < H; ++d) hold[d] = sm.h[a2][d];
            float hn[8], cn[8];
            #pragma unroll
            for (int q = 0; q < 8; ++q) {
                const int u = sub2 * 8 + q;
                float gi = sm.encB[u], gf = sm.encB[16 + u], gg = sm.encB[32 + u], go = sm.encB[48 + u];
                #pragma unroll
                for (int d = 0; d < H; ++d) {
                    const float e = emb[d], hd = hold[d];
                    gi = fmaf(e, sm.encWih[d * 64 + u],        gi); gi = fmaf(hd, sm.encWhh[d * 64 + u],        gi);
                    gf = fmaf(e, sm.encWih[d * 64 + 16 + u],   gf); gf = fmaf(hd, sm.encWhh[d * 64 + 16 + u],   gf);
                    gg = fmaf(e, sm.encWih[d * 64 + 32 + u],   gg); gg = fmaf(hd, sm.encWhh[d * 64 + 32 + u],   gg);
                    go = fmaf(e, sm.encWih[d * 64 + 48 + u],   go); go = fmaf(hd, sm.encWhh[d * 64 + 48 + u],   go);
                }
                const float cN = sigm(gf) * sm.c[a2][u] + sigm(gi) * tanh_f(gg);
                cn[q] = cN; hn[q] = sigm(go) * tanh_f(cN);
            }
            __syncwarp();   // agent thread-pairs are intra-warp
            #pragma unroll
            for (int q = 0; q < 8; ++q) { sm.h[a2][sub2 * 8 + q] = hn[q]; sm.c[a2][sub2 * 8 + q] = cn[q]; }
            __syncwarp();
        }
        #pragma unroll
        for (int q = 0; q < 8; ++q) sm.c[a2][sub2 * 8 + q] = 0.0f;
    }
    __syncthreads();

    // ---------------- autoregressive decoder ----------------
    for (int step = 0; step < PRED; ++step) {
        // decoder input embed + LSTM (2 threads/agent, tid<256)
        if (lstm_active) {
            float ctxv[H];
            #pragma unroll
            for (int d = 0; d < H; ++d) ctxv[d] = sm.ctx[a2][d];
            const float o0 = sm.outp[a2][0], o1 = sm.outp[a2][1];
            float emb[H];
            #pragma unroll
            for (int u = 0; u < H; ++u) {
                float acc = sm.decinB[u];
                #pragma unroll
                for (int d = 0; d < H; ++d) acc = fmaf(ctxv[d], sm.decinW[d * 16 + u], acc);
                acc = fmaf(o0, sm.decinW[256 + u], fmaf(o1, sm.decinW[272 + u], acc));
                emb[u] = fmaxf(acc, 0.0f);
            }
            float hold[H];
            #pragma unroll
            for (int d = 0; d < H; ++d) hold[d] = sm.h[a2][d];
            float hn[8], cn[8];
            #pragma unroll
            for (int q = 0; q < 8; ++q) {
                const int u = sub2 * 8 + q;
                float gi = sm.decB[u], gf = sm.decB[16 + u], gg = sm.decB[32 + u], go = sm.decB[48 + u];
                #pragma unroll
                for (int d = 0; d < H; ++d) {
                    const float e = emb[d], hd = hold[d];
                    gi = fmaf(e, sm.decWih[d * 64 + u],        gi); gi = fmaf(hd, sm.decWhh[d * 64 + u],        gi);
                    gf = fmaf(e, sm.decWih[d * 64 + 16 + u],   gf); gf = fmaf(hd, sm.decWhh[d * 64 + 16 + u],   gf);
                    gg = fmaf(e, sm.decWih[d * 64 + 32 + u],   gg); gg = fmaf(hd, sm.decWhh[d * 64 + 32 + u],   gg);
                    go = fmaf(e, sm.decWih[d * 64 + 48 + u],   go); go = fmaf(hd, sm.decWhh[d * 64 + 48 + u],   go);
                }
                const float cN = sigm(gf) * sm.c[a2][u] + sigm(gi) * tanh_f(gg);
                cn[q] = cN; hn[q] = sigm(go) * tanh_f(cN);
            }
            __syncthreads();   // all reads of old h/ctx complete
            #pragma unroll
            for (int q = 0; q < 8; ++q) { sm.h[a2][sub2 * 8 + q] = hn[q]; sm.c[a2][sub2 * 8 + q] = cn[q]; }
        } else {
            __syncthreads();
        }
        __syncwarp();

        // hjp[j][k] = h_j . W1h[:,k] + b1[k]  (2 threads/agent, 32 k's each;
        // needs only the pair's own h, completed intra-warp)
        if (lstm_active) {
            const int j = a2, k0 = sub2 * 32;
            float hv[H];
            #pragma unroll
            for (int d = 0; d < H; ++d) hv[d] = sm.h[j][d];
            #pragma unroll
            for (int kk = 0; kk < 32; ++kk) {
                const int k = k0 + kk;
                float acc = sm.b1[k];
                #pragma unroll
                for (int d = 0; d < H; ++d) acc = fmaf(hv[d], sm.W1h[d * 64 + k], acc);
                sm.hjp[j][k] = acc;
            }
        }
        for (int idx = tid; idx < NAGC * 17; idx += NTHREADS) (&sm.ctx[0][0])[idx] = 0.0f;
        __syncthreads();

        // ---- pooling: full tile-3 iterations, then an EXACT tile-1 tail ----
        if (mycnt > 0) {
            int   cur_i = -1;
            float acc[H];
            for (int t = 0; t < mymain; t += 3) {
                int pi[3], pj[3];
                #pragma unroll
                for (int e = 0; e < 3; ++e) {
                    const int pr = sm.plist[mystart + t + e];
                    pi[e] = pr >> 7; pj[e] = pr & 127;
                }
                float pe[3][H], m[3][H];
                #pragma unroll
                for (int e = 0; e < 3; ++e) {
                    const float dx = sm.curr[pi[e]][0] - sm.curr[pj[e]][0];
                    const float dy = sm.curr[pi[e]][1] - sm.curr[pj[e]][1];
                    #pragma unroll
                    for (int u = 0; u < H; ++u) {
                        pe[e][u] = fmaxf(fmaf(dx, sm.peW[u], fmaf(dy, sm.peW[16 + u], sm.peB[u])), 0.0f);
                        m[e][u]  = 0.0f;
                    }
                }
                const float* __restrict__ hj0 = sm.hjp[pj[0]];
                const float* __restrict__ hj1 = sm.hjp[pj[1]];
                const float* __restrict__ hj2 = sm.hjp[pj[2]];
                for (int k = 0; k < 64; ++k) {
                    const float4* w1q = reinterpret_cast<const float4*>(sm.W1pT + (k << 4));
                    const float4 wa = w1q[0], wb = w1q[1], wc = w1q[2], wd = w1q[3];
                    // 6 independent half-chains (3 pairs x 2 halves)
                    float a0a = hj0[k], a0b = 0.0f;
                    float a1a = hj1[k], a1b = 0.0f;
                    float a2a = hj2[k], a2b = 0.0f;
                    a0a = fmaf(pe[0][0],  wa.x, a0a); a0b = fmaf(pe[0][8],  wc.x, a0b);
                    a1a = fmaf(pe[1][0],  wa.x, a1a); a1b = fmaf(pe[1][8],  wc.x, a1b);
                    a2a = fmaf(pe[2][0],  wa.x, a2a); a2b = fmaf(pe[2][8],  wc.x, a2b);
                    a0a = fmaf(pe[0][1],  wa.y, a0a); a0b = fmaf(pe[0][9],  wc.y, a0b);
                    a1a = fmaf(pe[1][1],  wa.y, a1a); a1b = fmaf(pe[1][9],  wc.y, a1b);
                    a2a = fmaf(pe[2][1],  wa.y, a2a); a2b = fmaf(pe[2][9],  wc.y, a2b);
                    a0a = fmaf(pe[0][2],  wa.z, a0a); a0b = fmaf(pe[0][10], wc.z, a0b);
                    a1a = fmaf(pe[1][2],  wa.z, a1a); a1b = fmaf(pe[1][10], wc.z, a1b);
                    a2a = fmaf(pe[2][2],  wa.z, a2a); a2b = fmaf(pe[2][10], wc.z, a2b);
                    a0a = fmaf(pe[0][3],  wa.w, a0a); a0b = fmaf(pe[0][11], wc.w, a0b);
                    a1a = fmaf(pe[1][3],  wa.w, a1a); a1b = fmaf(pe[1][11], wc.w, a1b);
                    a2a = fmaf(pe[2][3],  wa.w, a2a); a2b = fmaf(pe[2][11], wc.w, a2b);
                    a0a = fmaf(pe[0][4],  wb.x, a0a); a0b = fmaf(pe[0][12], wd.x, a0b);
                    a1a = fmaf(pe[1][4],  wb.x, a1a); a1b = fmaf(pe[1][12], wd.x, a1b);
                    a2a = fmaf(pe[2][4],  wb.x, a2a); a2b = fmaf(pe[2][12], wd.x, a2b);
                    a0a = fmaf(pe[0][5],  wb.y, a0a); a0b = fmaf(pe[0][13], wd.y, a0b);
                    a1a = fmaf(pe[1][5],  wb.y, a1a); a1b = fmaf(pe[1][13], wd.y, a1b);
                    a2a = fmaf(pe[2][5],  wb.y, a2a); a2b = fmaf(pe[2][13], wd.y, a2b);
                    a0a = fmaf(pe[0][6],  wb.z, a0a); a0b = fmaf(pe[0][14], wd.z, a0b);
                    a1a = fmaf(pe[1][6],  wb.z, a1a); a1b = fmaf(pe[1][14], wd.z, a1b);
                    a2a = fmaf(pe[2][6],  wb.z, a2a); a2b = fmaf(pe[2][14], wd.z, a2b);
                    a0a = fmaf(pe[0][7],  wb.w, a0a); a0b = fmaf(pe[0][15], wd.w, a0b);
                    a1a = fmaf(pe[1][7],  wb.w, a1a); a1b = fmaf(pe[1][15], wd.w, a1b);
                    a2a = fmaf(pe[2][7],  wb.w, a2a); a2b = fmaf(pe[2][15], wd.w, a2b);
                    const float av0 = fmaxf(a0a + a0b, 0.0f);
                    const float av1 = fmaxf(a1a + a1b, 0.0f);
                    const float av2 = fmaxf(a2a + a2b, 0.0f);
                    const float4* w2q = reinterpret_cast<const float4*>(sm.W2 + (k << 4));
                    const float4 va = w2q[0], vb = w2q[1], vc = w2q[2], vd = w2q[3];
                    m[0][0]  = fmaf(av0, va.x, m[0][0]);  m[1][0]  = fmaf(av1, va.x, m[1][0]);  m[2][0]  = fmaf(av2, va.x, m[2][0]);
                    m[0][1]  = fmaf(av0, va.y, m[0][1]);  m[1][1]  = fmaf(av1, va.y, m[1][1]);  m[2][1]  = fmaf(av2, va.y, m[2][1]);
                    m[0][2]  = fmaf(av0, va.z, m[0][2]);  m[1][2]  = fmaf(av1, va.z, m[1][2]);  m[2][2]  = fmaf(av2, va.z, m[2][2]);
                    m[0][3]  = fmaf(av0, va.w, m[0][3]);  m[1][3]  = fmaf(av1, va.w, m[1][3]);  m[2][3]  = fmaf(av2, va.w, m[2][3]);
                    m[0][4]  = fmaf(av0, vb.x, m[0][4]);  m[1][4]  = fmaf(av1, vb.x, m[1][4]);  m[2][4]  = fmaf(av2, vb.x, m[2][4]);
                    m[0][5]  = fmaf(av0, vb.y, m[0][5]);  m[1][5]  = fmaf(av1, vb.y, m[1][5]);  m[2][5]  = fmaf(av2, vb.y, m[2][5]);
                    m[0][6]  = fmaf(av0, vb.z, m[0][6]);  m[1][6]  = fmaf(av1, vb.z, m[1][6]);  m[2][6]  = fmaf(av2, vb.z, m[2][6]);
                    m[0][7]  = fmaf(av0, vb.w, m[0][7]);  m[1][7]  = fmaf(av1, vb.w, m[1][7]);  m[2][7]  = fmaf(av2, vb.w, m[2][7]);
                    m[0][8]  = fmaf(av0, vc.x, m[0][8]);  m[1][8]  = fmaf(av1, vc.x, m[1][8]);  m[2][8]  = fmaf(av2, vc.x, m[2][8]);
                    m[0][9]  = fmaf(av0, vc.y, m[0][9]);  m[1][9]  = fmaf(av1, vc.y, m[1][9]);  m[2][9]  = fmaf(av2, vc.y, m[2][9]);
                    m[0][10] = fmaf(av0, vc.z, m[0][10]); m[1][10] = fmaf(av1, vc.z, m[1][10]); m[2][10] = fmaf(av2, vc.z, m[2][10]);
                    m[0][11] = fmaf(av0, vc.w, m[0][11]); m[1][11] = fmaf(av1, vc.w, m[1][11]); m[2][11] = fmaf(av2, vc.w, m[2][11]);
                    m[0][12] = fmaf(av0, vd.x, m[0][12]); m[1][12] = fmaf(av1, vd.x, m[1][12]); m[2][12] = fmaf(av2, vd.x, m[2][12]);
                    m[0][13] = fmaf(av0, vd.y, m[0][13]); m[1][13] = fmaf(av1, vd.y, m[1][13]); m[2][13] = fmaf(av2, vd.y, m[2][13]);
                    m[0][14] = fmaf(av0, vd.z, m[0][14]); m[1][14] = fmaf(av1, vd.z, m[1][14]); m[2][14] = fmaf(av2, vd.z, m[2][14]);
                    m[0][15] = fmaf(av0, vd.w, m[0][15]); m[1][15] = fmaf(av1, vd.w, m[1][15]); m[2][15] = fmaf(av2, vd.w, m[2][15]);
                }
                // epilogue: segment accumulation over i (list i-sorted)
                #pragma unroll
                for (int e = 0; e < 3; ++e) {
                    if (pi[e] == cur_i) {
                        #pragma unroll
                        for (int u = 0; u < H; ++u)
                            acc[u] += fmaxf(m[e][u] + sm.b2[u], 0.0f);
                    } else {
                        if (cur_i >= 0) {
                            #pragma unroll
                            for (int u = 0; u < H; ++u) atomicAdd(&sm.ctx[cur_i][u], acc[u]);
                        }
                        cur_i = pi[e];
                        #pragma unroll
                        for (int u = 0; u < H; ++u)
                            acc[u] = fmaxf(m[e][u] + sm.b2[u], 0.0f);
                    }
                }
            }
            // exact tail: up to 2 real pairs, tile-1 body (two half-chains)
            for (int t = mymain; t < mycnt; ++t) {
                const int pr = sm.plist[mystart + t];
                const int i = pr >> 7, j = pr & 127;
                const float dx = sm.curr[i][0] - sm.curr[j][0];
                const float dy = sm.curr[i][1] - sm.curr[j][1];
                float pe[H], m[H];
                #pragma unroll
                for (int u = 0; u < H; ++u) {
                    pe[u] = fmaxf(fmaf(dx, sm.peW[u], fmaf(dy, sm.peW[16 + u], sm.peB[u])), 0.0f);
                    m[u]  = 0.0f;
                }
                const float* __restrict__ hjrow = sm.hjp[j];
                for (int k = 0; k < 64; ++k) {
                    const float4* w1q = reinterpret_cast<const float4*>(sm.W1pT + (k << 4));
                    const float4 wa = w1q[0], wb = w1q[1], wc = w1q[2], wd = w1q[3];
                    float aA = hjrow[k], aB = 0.0f;
                    aA = fmaf(pe[0],  wa.x, aA); aB = fmaf(pe[8],  wc.x, aB);
                    aA = fmaf(pe[1],  wa.y, aA); aB = fmaf(pe[9],  wc.y, aB);
                    aA = fmaf(pe[2],  wa.z, aA); aB = fmaf(pe[10], wc.z, aB);
                    aA = fmaf(pe[3],  wa.w, aA); aB = fmaf(pe[11], wc.w, aB);
                    aA = fmaf(pe[4],  wb.x, aA); aB = fmaf(pe[12], wd.x, aB);
                    aA = fmaf(pe[5],  wb.y, aA); aB = fmaf(pe[13], wd.y, aB);
                    aA = fmaf(pe[6],  wb.z, aA); aB = fmaf(pe[14], wd.z, aB);
                    aA = fmaf(pe[7],  wb.w, aA); aB = fmaf(pe[15], wd.w, aB);
                    const float av = fmaxf(aA + aB, 0.0f);
                    const float4* w2q = reinterpret_cast<const float4*>(sm.W2 + (k << 4));
                    const float4 va = w2q[0], vb = w2q[1], vc = w2q[2], vd = w2q[3];
                    m[0]  = fmaf(av, va.x, m[0]);  m[1]  = fmaf(av, va.y, m[1]);
                    m[2]  = fmaf(av, va.z, m[2]);  m[3]  = fmaf(av, va.w, m[3]);
                    m[4]  = fmaf(av, vb.x, m[4]);  m[5]  = fmaf(av, vb.y, m[5]);
                    m[6]  = fmaf(av, vb.z, m[6]);  m[7]  = fmaf(av, vb.w, m[7]);
                    m[8]  = fmaf(av, vc.x, m[8]);  m[9]  = fmaf(av, vc.y, m[9]);
                    m[10] = fmaf(av, vc.z, m[10]); m[11] = fmaf(av, vc.w, m[11]);
                    m[12] = fmaf(av, vd.x, m[12]); m[13] = fmaf(av, vd.y, m[13]);
                    m[14] = fmaf(av, vd.z, m[14]); m[15] = fmaf(av, vd.w, m[15]);
                }
                if (i == cur_i) {
                    #pragma unroll
                    for (int u = 0; u < H; ++u) acc[u] += fmaxf(m[u] + sm.b2[u], 0.0f);
                } else {
                    if (cur_i >= 0) {
                        #pragma unroll
                        for (int u = 0; u < H; ++u) atomicAdd(&sm.ctx[cur_i][u], acc[u]);
                    }
                    cur_i = i;
                    #pragma unroll
                    for (int u = 0; u < H; ++u) acc[u] = fmaxf(m[u] + sm.b2[u], 0.0f);
                }
            }
            if (cur_i >= 0) {
                #pragma unroll
                for (int u = 0; u < H; ++u) atomicAdd(&sm.ctx[cur_i][u], acc[u]);
            }
        }
        __syncthreads();

        // output head (one thread per agent, both samples)
        if (tid < NAGC) {
            float hv[H], hh[H];
            #pragma unroll
            for (int u = 0; u < H; ++u) hv[u] = sm.h[tid][u] + sm.ctx[tid][u];
            const float g0 = sm.goal[tid][0], g1 = sm.goal[tid][1];
            #pragma unroll
            for (int u = 0; u < H; ++u) {
                float acc = sm.h2p1B[u];
                #pragma unroll
                for (int d = 0; d < H; ++d) acc = fmaf(hv[d], sm.h2p1W[d * 16 + u], acc);
                acc = fmaf(g0, sm.h2p1W[256 + u], fmaf(g1, sm.h2p1W[272 + u], acc));
                hh[u] = fmaxf(acc, 0.0f);
            }
            float mu0 = sm.h2p2B[0], mu1 = sm.h2p2B[1];
            #pragma unroll
            for (int d = 0; d < H; ++d) {
                mu0 = fmaf(hh[d], sm.h2p2W[d * 4 + 0], mu0);
                mu1 = fmaf(hh[d], sm.h2p2W[d * 4 + 1], mu1);
            }
            const int b = gb + tid;
            out[(step * BTOT + b) * 2 + 0] = mu0;
            out[(step * BTOT + b) * 2 + 1] = mu1;
            sm.outp[tid][0] = mu0; sm.outp[tid][1] = mu1;
            sm.curr[tid][0] += mu0; sm.curr[tid][1] += mu1;
        }
        __syncthreads();
    }
}

extern "C" void kernel_launch(void* const* d_in, const int* in_sizes, int n_in,
                              void* d_out, int out_size)
{
    (void)in_sizes; (void)n_in;
    cudaFuncSetAttribute(traj_ar_kernel, cudaFuncAttributeMaxDynamicSharedMemorySize,
                         (int)sizeof(Smem));
    traj_ar_kernel<<<NCTAS, NTHREADS, sizeof(Smem)>>>(
        (const float*)d_in[0],
        (const float*)d_in[1],
        (const float*)d_in[2],
        (const float*)d_in[4],  (const float*)d_in[5],
        (const float*)d_in[6],  (const float*)d_in[7],  (const float*)d_in[8],
        (const float*)d_in[9],  (const float*)d_in[10],
        (const float*)d_in[11], (const float*)d_in[12], (const float*)d_in[13],
        (const float*)d_in[14], (const float*)d_in[15],
        (const float*)d_in[16], (const float*)d_in[17],
        (const float*)d_in[18], (const float*)d_in[19],
        (const float*)d_in[20], (const float*)d_in[21],
        (const float*)d_in[22], (const float*)d_in[23],
        (const int*)d_in[24],
        (float*)d_out, out_size);
}

// round 17
// speedup vs baseline: 1.0884x; 1.0884x over previous
#include <cuda_runtime.h>

// TrajectoryGeneratorAR_goal: S=256 rollouts x N=64 agents, OBS=8 encoder LSTM
// steps, PRED=12 autoregressive decoder steps with pairwise pooling net.
// Round 17 = R15 winner (1428us: 128 CTAs x 384 thr, 2 samples/CTA, tile-3
// pooling with clamped pads, 168 regs) + one micro-cut: the ctx-zero sweep
// (384 threads x 6 STS in the serial hjp phase) is folded into the LSTM
// phase — each LSTM thread reads its own ctx row then zeroes its half.
// Ordering: pool(t-1) write -> head(t-1) read -> LSTM(t) read+zero -> pool(t).

namespace {

constexpr int S_BATCH  = 256;
constexpr int NAG      = 64;     // agents per sample
constexpr int NAGC     = 128;    // agents per CTA (2 samples)
constexpr int BTOT     = S_BATCH * NAG;   // 16384
constexpr int OBS      = 8;
constexpr int PRED     = 12;
constexpr int H        = 16;
constexpr int NTHREADS = 384;
constexpr int NCTAS    = S_BATCH / 2;     // 128
constexpr int MAXPAIRS = NAGC * NAG;      // 8192

struct __align__(16) Smem {
    float h[NAGC][17];
    float c[NAGC][17];
    float ctx[NAGC][17];
    float hjp[NAGC][65];
    float curr[NAGC][2];
    float outp[NAGC][2];
    float goal[NAGC][2];
    unsigned long long nmask[NAGC];
    int   pfx[NAGC + 1];
    unsigned short plist[MAXPAIRS];   // (i<<7)|j, sorted by i
    alignas(16) float embW[32];
    alignas(16) float embB[16];
    alignas(16) float encWih[16*64];
    alignas(16) float encWhh[16*64];
    alignas(16) float encB[64];
    alignas(16) float decinW[18*16];
    alignas(16) float decinB[16];
    alignas(16) float decWih[16*64];
    alignas(16) float decWhh[16*64];
    alignas(16) float decB[64];
    alignas(16) float peW[32];
    alignas(16) float peB[16];
    alignas(16) float W1pT[64*16];   // [k][d]  (pool_W1 rows 0..15, transposed)
    alignas(16) float W1h [16*64];   // [d][k]  (pool_W1 rows 16..31)
    alignas(16) float b1  [64];
    alignas(16) float W2  [64*16];   // [k][u]
    alignas(16) float b2  [16];
    alignas(16) float h2p1W[18*16];
    alignas(16) float h2p1B[16];
    alignas(16) float h2p2W[16*4];
    alignas(16) float h2p2B[4];
};

__device__ __forceinline__ float sigm(float x)   { return 1.0f / (1.0f + __expf(-x)); }
__device__ __forceinline__ float tanh_f(float x) { return 2.0f / (1.0f + __expf(-2.0f * x)) - 1.0f; }

__device__ __forceinline__ void cpw(float* dst, const float* src, int n, int tid) {
    for (int k = tid; k < n; k += NTHREADS) dst[k] = src[k];
}

} // namespace

__global__ __launch_bounds__(NTHREADS, 1)
void traj_ar_kernel(
    const float* __restrict__ traj_rel,
    const float* __restrict__ obs_pos,
    const float* __restrict__ goal_g,
    const float* __restrict__ embW, const float* __restrict__ embB,
    const float* __restrict__ encWih, const float* __restrict__ encWhh, const float* __restrict__ encB,
    const float* __restrict__ decinW, const float* __restrict__ decinB,
    const float* __restrict__ decWih, const float* __restrict__ decWhh, const float* __restrict__ decB,
    const float* __restrict__ peW, const float* __restrict__ peB,
    const float* __restrict__ W1, const float* __restrict__ b1,
    const float* __restrict__ W2, const float* __restrict__ b2,
    const float* __restrict__ h2p1W, const float* __restrict__ h2p1B,
    const float* __restrict__ h2p2W, const float* __restrict__ h2p2B,
    const int* __restrict__ nei,
    float* __restrict__ out, int out_size)
{
    extern __shared__ unsigned char smem_raw[];
    Smem& sm = *reinterpret_cast<Smem*>(smem_raw);
    const int tid = threadIdx.x;
    const int sb  = blockIdx.x;           // CTA handles samples 2sb, 2sb+1
    const int gb  = sb * NAGC;

    if (sb == 0 && tid == 0) {
        for (int idx = PRED * BTOT * 2; idx < out_size; ++idx) out[idx] = 0.0f;
    }

    // ---------------- weight staging + state init ----------------
    cpw(sm.embW,  embW,  32,  tid);  cpw(sm.embB,  embB,  16, tid);
    cpw(sm.encWih, encWih, 1024, tid); cpw(sm.encWhh, encWhh, 1024, tid); cpw(sm.encB, encB, 64, tid);
    cpw(sm.decinW, decinW, 288, tid);  cpw(sm.decinB, decinB, 16, tid);
    cpw(sm.decWih, decWih, 1024, tid); cpw(sm.decWhh, decWhh, 1024, tid); cpw(sm.decB, decB, 64, tid);
    cpw(sm.peW, peW, 32, tid); cpw(sm.peB, peB, 16, tid);
    for (int idx = tid; idx < 1024; idx += NTHREADS) {
        const int k = idx >> 4, d = idx & 15;
        sm.W1pT[idx] = W1[d * 64 + k];
    }
    cpw(sm.W1h, W1 + 1024, 1024, tid);
    cpw(sm.b1, b1, 64, tid); cpw(sm.W2, W2, 1024, tid); cpw(sm.b2, b2, 16, tid);
    cpw(sm.h2p1W, h2p1W, 288, tid); cpw(sm.h2p1B, h2p1B, 16, tid);
    cpw(sm.h2p2W, h2p2W, 64, tid);  cpw(sm.h2p2B, h2p2B, 4, tid);

    for (int idx = tid; idx < NAGC * 17; idx += NTHREADS) {
        (&sm.h[0][0])[idx] = 0.0f; (&sm.c[0][0])[idx] = 0.0f; (&sm.ctx[0][0])[idx] = 0.0f;
    }
    if (tid < NAGC) {
        sm.nmask[tid] = 0ull;
        const int b = gb + tid;
        const float c0 = obs_pos[((OBS - 1) * BTOT + b) * 2 + 0];
        const float c1 = obs_pos[((OBS - 1) * BTOT + b) * 2 + 1];
        sm.curr[tid][0] = c0; sm.curr[tid][1] = c1;
        sm.outp[tid][0] = traj_rel[((OBS - 1) * BTOT + b) * 2 + 0];
        sm.outp[tid][1] = traj_rel[((OBS - 1) * BTOT + b) * 2 + 1];
        sm.goal[tid][0] = goal_g[b * 2 + 0] - c0;
        sm.goal[tid][1] = goal_g[b * 2 + 1] - c1;
    }
    __syncthreads();
    {   // neighbor masks for both samples: row i (0..127), local j (0..63)
        const int base = gb * NAG;
        for (int flat = tid; flat < NAGC * NAG; flat += NTHREADS) {
            if (nei[base + flat] != 0)
                atomicOr(&sm.nmask[flat >> 6], 1ull << (flat & 63));
        }
    }
    __syncthreads();
    // ---- compacted (i, j_global) pair list, sorted by i ----
    if (tid == 0) {
        int run = 0;
        for (int i = 0; i < NAGC; ++i) { sm.pfx[i] = run; run += __popcll(sm.nmask[i]); }
        sm.pfx[NAGC] = run;
    }
    __syncthreads();
    if (tid < NAGC) {
        unsigned long long m = sm.nmask[tid];
        int w = sm.pfx[tid];
        const int jbase = tid & 64;                // sample offset for j
        const unsigned short ibase = (unsigned short)(tid << 7);
        while (m) {
            const int j = __ffsll((long long)m) - 1;
            m &= m - 1;
            sm.plist[w++] = (unsigned short)(ibase | (unsigned short)(jbase + j));
        }
    }
    __syncthreads();
    const int P       = sm.pfx[NAGC];
    const int pbase   = P / NTHREADS;
    const int prem    = P - pbase * NTHREADS;
    const int mystart = tid * pbase + (tid < prem ? tid : prem);
    const int mycnt   = pbase + (tid < prem ? 1 : 0);

    // LSTM phase layout: 2 threads per agent (tid < 256), 8 gate units each
    const int a2   = tid >> 1;
    const int sub2 = tid & 1;
    const bool lstm_active = (tid < 2 * NAGC);

    // ---------------- history encoder ----------------
    if (lstm_active) {
        for (int t = 0; t < OBS; ++t) {
            const int b = gb + a2;
            const float x0 = traj_rel[(t * BTOT + b) * 2 + 0];
            const float x1 = traj_rel[(t * BTOT + b) * 2 + 1];
            float emb[H];
            #pragma unroll
            for (int u = 0; u < H; ++u)
                emb[u] = fmaxf(fmaf(x0, sm.embW[u], fmaf(x1, sm.embW[16 + u], sm.embB[u])), 0.0f);
            float hold[H];
            #pragma unroll
            for (int d = 0; d < H; ++d) hold[d] = sm.h[a2][d];
            float hn[8], cn[8];
            #pragma unroll
            for (int q = 0; q < 8; ++q) {
                const int u = sub2 * 8 + q;
                float gi = sm.encB[u], gf = sm.encB[16 + u], gg = sm.encB[32 + u], go = sm.encB[48 + u];
                #pragma unroll
                for (int d = 0; d < H; ++d) {
                    const float e = emb[d], hd = hold[d];
                    gi = fmaf(e, sm.encWih[d * 64 + u],        gi); gi = fmaf(hd, sm.encWhh[d * 64 + u],        gi);
                    gf = fmaf(e, sm.encWih[d * 64 + 16 + u],   gf); gf = fmaf(hd, sm.encWhh[d * 64 + 16 + u],   gf);
                    gg = fmaf(e, sm.encWih[d * 64 + 32 + u],   gg); gg = fmaf(hd, sm.encWhh[d * 64 + 32 + u],   gg);
                    go = fmaf(e, sm.encWih[d * 64 + 48 + u],   go); go = fmaf(hd, sm.encWhh[d * 64 + 48 + u],   go);
                }
                const float cN = sigm(gf) * sm.c[a2][u] + sigm(gi) * tanh_f(gg);
                cn[q] = cN; hn[q] = sigm(go) * tanh_f(cN);
            }
            __syncwarp();   // agent thread-pairs are intra-warp
            #pragma unroll
            for (int q = 0; q < 8; ++q) { sm.h[a2][sub2 * 8 + q] = hn[q]; sm.c[a2][sub2 * 8 + q] = cn[q]; }
            __syncwarp();
        }
        #pragma unroll
        for (int q = 0; q < 8; ++q) sm.c[a2][sub2 * 8 + q] = 0.0f;
    }
    __syncthreads();

    // ---------------- autoregressive decoder ----------------
    for (int step = 0; step < PRED; ++step) {
        // decoder input embed + LSTM (2 threads/agent, tid<256);
        // each thread reads its ctx row then zeroes its half (fold of the
        // old ctx-zero sweep; pool of this step re-accumulates from zero)
        if (lstm_active) {
            float ctxv[H];
            #pragma unroll
            for (int d = 0; d < H; ++d) ctxv[d] = sm.ctx[a2][d];
            // zero my half of ctx[a2][0..17) — sub2=0: [0,9), sub2=1: [9,17)
            {
                const int z0 = sub2 ? 9 : 0;
                const int z1 = sub2 ? 17 : 9;
                for (int z = z0; z < z1; ++z) sm.ctx[a2][z] = 0.0f;
            }
            const float o0 = sm.outp[a2][0], o1 = sm.outp[a2][1];
            float emb[H];
            #pragma unroll
            for (int u = 0; u < H; ++u) {
                float acc = sm.decinB[u];
                #pragma unroll
                for (int d = 0; d < H; ++d) acc = fmaf(ctxv[d], sm.decinW[d * 16 + u], acc);
                acc = fmaf(o0, sm.decinW[256 + u], fmaf(o1, sm.decinW[272 + u], acc));
                emb[u] = fmaxf(acc, 0.0f);
            }
            float hold[H];
            #pragma unroll
            for (int d = 0; d < H; ++d) hold[d] = sm.h[a2][d];
            float hn[8], cn[8];
            #pragma unroll
            for (int q = 0; q < 8; ++q) {
                const int u = sub2 * 8 + q;
                float gi = sm.decB[u], gf = sm.decB[16 + u], gg = sm.decB[32 + u], go = sm.decB[48 + u];
                #pragma unroll
                for (int d = 0; d < H; ++d) {
                    const float e = emb[d], hd = hold[d];
                    gi = fmaf(e, sm.decWih[d * 64 + u],        gi); gi = fmaf(hd, sm.decWhh[d * 64 + u],        gi);
                    gf = fmaf(e, sm.decWih[d * 64 + 16 + u],   gf); gf = fmaf(hd, sm.decWhh[d * 64 + 16 + u],   gf);
                    gg = fmaf(e, sm.decWih[d * 64 + 32 + u],   gg); gg = fmaf(hd, sm.decWhh[d * 64 + 32 + u],   gg);
                    go = fmaf(e, sm.decWih[d * 64 + 48 + u],   go); go = fmaf(hd, sm.decWhh[d * 64 + 48 + u],   go);
                }
                const float cN = sigm(gf) * sm.c[a2][u] + sigm(gi) * tanh_f(gg);
                cn[q] = cN; hn[q] = sigm(go) * tanh_f(cN);
            }
            __syncthreads();   // all reads of old h/ctx complete
            #pragma unroll
            for (int q = 0; q < 8; ++q) { sm.h[a2][sub2 * 8 + q] = hn[q]; sm.c[a2][sub2 * 8 + q] = cn[q]; }
        } else {
            __syncthreads();
        }
        __syncwarp();

        // hjp[j][k] = h_j . W1h[:,k] + b1[k]  (2 threads/agent, 32 k's each;
        // needs only the pair's own h, completed intra-warp)
        if (lstm_active) {
            const int j = a2, k0 = sub2 * 32;
            float hv[H];
            #pragma unroll
            for (int d = 0; d < H; ++d) hv[d] = sm.h[j][d];
            #pragma unroll
            for (int kk = 0; kk < 32; ++kk) {
                const int k = k0 + kk;
                float acc = sm.b1[k];
                #pragma unroll
                for (int d = 0; d < H; ++d) acc = fmaf(hv[d], sm.W1h[d * 64 + k], acc);
                sm.hjp[j][k] = acc;
            }
        }
        __syncthreads();

        // ---- pooling: tiles of 3 pairs (clamped zero-weight pads),
        //      6 independent FMA half-chains per k ----
        if (mycnt > 0) {
            int   cur_i = -1;
            float acc[H];
            for (int t = 0; t < mycnt; t += 3) {
                int pi[3], pj[3];
                float pw[3];
                #pragma unroll
                for (int e = 0; e < 3; ++e) {
                    const int tt  = t + e;
                    const int idx = mystart + (tt < mycnt ? tt : mycnt - 1);
                    const int pr  = sm.plist[idx];
                    pi[e] = pr >> 7; pj[e] = pr & 127;
                    pw[e] = (tt < mycnt) ? 1.0f : 0.0f;
                }
                float pe[3][H], m[3][H];
                #pragma unroll
                for (int e = 0; e < 3; ++e) {
                    const float dx = sm.curr[pi[e]][0] - sm.curr[pj[e]][0];
                    const float dy = sm.curr[pi[e]][1] - sm.curr[pj[e]][1];
                    #pragma unroll
                    for (int u = 0; u < H; ++u) {
                        pe[e][u] = fmaxf(fmaf(dx, sm.peW[u], fmaf(dy, sm.peW[16 + u], sm.peB[u])), 0.0f);
                        m[e][u]  = 0.0f;
                    }
                }
                const float* __restrict__ hj0 = sm.hjp[pj[0]];
                const float* __restrict__ hj1 = sm.hjp[pj[1]];
                const float* __restrict__ hj2 = sm.hjp[pj[2]];
                for (int k = 0; k < 64; ++k) {
                    const float4* w1q = reinterpret_cast<const float4*>(sm.W1pT + (k << 4));
                    const float4 wa = w1q[0], wb = w1q[1], wc = w1q[2], wd = w1q[3];
                    // 6 independent half-chains (3 pairs x 2 halves)
                    float a0a = hj0[k], a0b = 0.0f;
                    float a1a = hj1[k], a1b = 0.0f;
                    float a2a = hj2[k], a2b = 0.0f;
                    a0a = fmaf(pe[0][0],  wa.x, a0a); a0b = fmaf(pe[0][8],  wc.x, a0b);
                    a1a = fmaf(pe[1][0],  wa.x, a1a); a1b = fmaf(pe[1][8],  wc.x, a1b);
                    a2a = fmaf(pe[2][0],  wa.x, a2a); a2b = fmaf(pe[2][8],  wc.x, a2b);
                    a0a = fmaf(pe[0][1],  wa.y, a0a); a0b = fmaf(pe[0][9],  wc.y, a0b);
                    a1a = fmaf(pe[1][1],  wa.y, a1a); a1b = fmaf(pe[1][9],  wc.y, a1b);
                    a2a = fmaf(pe[2][1],  wa.y, a2a); a2b = fmaf(pe[2][9],  wc.y, a2b);
                    a0a = fmaf(pe[0][2],  wa.z, a0a); a0b = fmaf(pe[0][10], wc.z, a0b);
                    a1a = fmaf(pe[1][2],  wa.z, a1a); a1b = fmaf(pe[1][10], wc.z, a1b);
                    a2a = fmaf(pe[2][2],  wa.z, a2a); a2b = fmaf(pe[2][10], wc.z, a2b);
                    a0a = fmaf(pe[0][3],  wa.w, a0a); a0b = fmaf(pe[0][11], wc.w, a0b);
                    a1a = fmaf(pe[1][3],  wa.w, a1a); a1b = fmaf(pe[1][11], wc.w, a1b);
                    a2a = fmaf(pe[2][3],  wa.w, a2a); a2b = fmaf(pe[2][11], wc.w, a2b);
                    a0a = fmaf(pe[0][4],  wb.x, a0a); a0b = fmaf(pe[0][12], wd.x, a0b);
                    a1a = fmaf(pe[1][4],  wb.x, a1a); a1b = fmaf(pe[1][12], wd.x, a1b);
                    a2a = fmaf(pe[2][4],  wb.x, a2a); a2b = fmaf(pe[2][12], wd.x, a2b);
                    a0a = fmaf(pe[0][5],  wb.y, a0a); a0b = fmaf(pe[0][13], wd.y, a0b);
                    a1a = fmaf(pe[1][5],  wb.y, a1a); a1b = fmaf(pe[1][13], wd.y, a1b);
                    a2a = fmaf(pe[2][5],  wb.y, a2a); a2b = fmaf(pe[2][13], wd.y, a2b);
                    a0a = fmaf(pe[0][6],  wb.z, a0a); a0b = fmaf(pe[0][14], wd.z, a0b);
                    a1a = fmaf(pe[1][6],  wb.z, a1a); a1b = fmaf(pe[1][14], wd.z, a1b);
                    a2a = fmaf(pe[2][6],  wb.z, a2a); a2b = fmaf(pe[2][14], wd.z, a2b);
                    a0a = fmaf(pe[0][7],  wb.w, a0a); a0b = fmaf(pe[0][15], wd.w, a0b);
                    a1a = fmaf(pe[1][7],  wb.w, a1a); a1b = fmaf(pe[1][15], wd.w, a1b);
                    a2a = fmaf(pe[2][7],  wb.w, a2a); a2b = fmaf(pe[2][15], wd.w, a2b);
                    const float av0 = fmaxf(a0a + a0b, 0.0f);
                    const float av1 = fmaxf(a1a + a1b, 0.0f);
                    const float av2 = fmaxf(a2a + a2b, 0.0f);
                    const float4* w2q = reinterpret_cast<const float4*>(sm.W2 + (k << 4));
                    const float4 va = w2q[0], vb = w2q[1], vc = w2q[2], vd = w2q[3];
                    m[0][0]  = fmaf(av0, va.x, m[0][0]);  m[1][0]  = fmaf(av1, va.x, m[1][0]);  m[2][0]  = fmaf(av2, va.x, m[2][0]);
                    m[0][1]  = fmaf(av0, va.y, m[0][1]);  m[1][1]  = fmaf(av1, va.y, m[1][1]);  m[2][1]  = fmaf(av2, va.y, m[2][1]);
                    m[0][2]  = fmaf(av0, va.z, m[0][2]);  m[1][2]  = fmaf(av1, va.z, m[1][2]);  m[2][2]  = fmaf(av2, va.z, m[2][2]);
                    m[0][3]  = fmaf(av0, va.w, m[0][3]);  m[1][3]  = fmaf(av1, va.w, m[1][3]);  m[2][3]  = fmaf(av2, va.w, m[2][3]);
                    m[0][4]  = fmaf(av0, vb.x, m[0][4]);  m[1][4]  = fmaf(av1, vb.x, m[1][4]);  m[2][4]  = fmaf(av2, vb.x, m[2][4]);
                    m[0][5]  = fmaf(av0, vb.y, m[0][5]);  m[1][5]  = fmaf(av1, vb.y, m[1][5]);  m[2][5]  = fmaf(av2, vb.y, m[2][5]);
                    m[0][6]  = fmaf(av0, vb.z, m[0][6]);  m[1][6]  = fmaf(av1, vb.z, m[1][6]);  m[2][6]  = fmaf(av2, vb.z, m[2][6]);
                    m[0][7]  = fmaf(av0, vb.w, m[0][7]);  m[1][7]  = fmaf(av1, vb.w, m[1][7]);  m[2][7]  = fmaf(av2, vb.w, m[2][7]);
                    m[0][8]  = fmaf(av0, vc.x, m[0][8]);  m[1][8]  = fmaf(av1, vc.x, m[1][8]);  m[2][8]  = fmaf(av2, vc.x, m[2][8]);
                    m[0][9]  = fmaf(av0, vc.y, m[0][9]);  m[1][9]  = fmaf(av1, vc.y, m[1][9]);  m[2][9]  = fmaf(av2, vc.y, m[2][9]);
                    m[0][10] = fmaf(av0, vc.z, m[0][10]); m[1][10] = fmaf(av1, vc.z, m[1][10]); m[2][10] = fmaf(av2, vc.z, m[2][10]);
                    m[0][11] = fmaf(av0, vc.w, m[0][11]); m[1][11] = fmaf(av1, vc.w, m[1][11]); m[2][11] = fmaf(av2, vc.w, m[2][11]);
                    m[0][12] = fmaf(av0, vd.x, m[0][12]); m[1][12] = fmaf(av1, vd.x, m[1][12]); m[2][12] = fmaf(av2, vd.x, m[2][12]);
                    m[0][13] = fmaf(av0, vd.y, m[0][13]); m[1][13] = fmaf(av1, vd.y, m[1][13]); m[2][13] = fmaf(av2, vd.y, m[2][13]);
                    m[0][14] = fmaf(av0, vd.z, m[0][14]); m[1][14] = fmaf(av1, vd.z, m[1][14]); m[2][14] = fmaf(av2, vd.z, m[2][14]);
                    m[0][15] = fmaf(av0, vd.w, m[0][15]); m[1][15] = fmaf(av1, vd.w, m[1][15]); m[2][15] = fmaf(av2, vd.w, m[2][15]);
                }
                // epilogue: segment accumulation over i (list i-sorted; pads
                // duplicate the last real pair's i so they never open a segment)
                #pragma unroll
                for (int e = 0; e < 3; ++e) {
                    if (pi[e] == cur_i) {
                        #pragma unroll
                        for (int u = 0; u < H; ++u)
                            acc[u] = fmaf(pw[e], fmaxf(m[e][u] + sm.b2[u], 0.0f), acc[u]);
                    } else {
                        if (cur_i >= 0) {
                            #pragma unroll
                            for (int u = 0; u < H; ++u) atomicAdd(&sm.ctx[cur_i][u], acc[u]);
                        }
                        cur_i = pi[e];
                        #pragma unroll
                        for (int u = 0; u < H; ++u)
                            acc[u] = pw[e] * fmaxf(m[e][u] + sm.b2[u], 0.0f);
                    }
                }
            }
            if (cur_i >= 0) {
                #pragma unroll
                for (int u = 0; u < H; ++u) atomicAdd(&sm.ctx[cur_i][u], acc[u]);
            }
        }
        __syncthreads();

        // output head (one thread per agent, both samples)
        if (tid < NAGC) {
            float hv[H], hh[H];
            #pragma unroll
            for (int u = 0; u < H; ++u) hv[u] = sm.h[tid][u] + sm.ctx[tid][u];
            const float g0 = sm.goal[tid][0], g1 = sm.goal[tid][1];
            #pragma unroll
            for (int u = 0; u < H; ++u) {
                float acc = sm.h2p1B[u];
                #pragma unroll
                for (int d = 0; d < H; ++d) acc = fmaf(hv[d], sm.h2p1W[d * 16 + u], acc);
                acc = fmaf(g0, sm.h2p1W[256 + u], fmaf(g1, sm.h2p1W[272 + u], acc));
                hh[u] = fmaxf(acc, 0.0f);
            }
            float mu0 = sm.h2p2B[0], mu1 = sm.h2p2B[1];
            #pragma unroll
            for (int d = 0; d < H; ++d) {
                mu0 = fmaf(hh[d], sm.h2p2W[d * 4 + 0], mu0);
                mu1 = fmaf(hh[d], sm.h2p2W[d * 4 + 1], mu1);
            }
            const int b = gb + tid;
            out[(step * BTOT + b) * 2 + 0] = mu0;
            out[(step * BTOT + b) * 2 + 1] = mu1;
            sm.outp[tid][0] = mu0; sm.outp[tid][1] = mu1;
            sm.curr[tid][0] += mu0; sm.curr[tid][1] += mu1;
        }
        __syncthreads();
    }
}

extern "C" void kernel_launch(void* const* d_in, const int* in_sizes, int n_in,
                              void* d_out, int out_size)
{
    (void)in_sizes; (void)n_in;
    cudaFuncSetAttribute(traj_ar_kernel, cudaFuncAttributeMaxDynamicSharedMemorySize,
                         (int)sizeof(Smem));
    traj_ar_kernel<<<NCTAS, NTHREADS, sizeof(Smem)>>>(
        (const float*)d_in[0],
        (const float*)d_in[1],
        (const float*)d_in[2],
        (const float*)d_in[4],  (const float*)d_in[5],
        (const float*)d_in[6],  (const float*)d_in[7],  (const float*)d_in[8],
        (const float*)d_in[9],  (const float*)d_in[10],
        (const float*)d_in[11], (const float*)d_in[12], (const float*)d_in[13],
        (const float*)d_in[14], (const float*)d_in[15],
        (const float*)d_in[16], (const float*)d_in[17],
        (const float*)d_in[18], (const float*)d_in[19],
        (const float*)d_in[20], (const float*)d_in[21],
        (const float*)d_in[22], (const float*)d_in[23],
        (const int*)d_in[24],
        (float*)d_out, out_size);
}